// round 1
// baseline (speedup 1.0000x reference)
#include <cuda_runtime.h>

#define BB  2
#define SS  2048
#define DD  1024
#define HH  16
#define HDD 64
#define NT  (BB * SS)   // 4096 tokens

// ---------------- scratch (no allocation allowed) ----------------
__device__ float g_q[NT * DD];    // [B,H,S,HD]
__device__ float g_k[NT * DD];    // [B,H,S,HD]
__device__ float g_v[NT * DD];    // [B,H,S,HD]
__device__ float g_ctx[NT * DD];  // [token, D]
__device__ float g_x[NT * DD];    // proj + residual, pre-LN

// =================================================================
// Classic 128x128x8 SGEMM, 256 threads, 8x8 per thread.
// A: [M=4096, K=1024] row-major.  W: [K=1024, N=1024] row-major.
// mode 0: out[(b,h,s,d)] = acc + bias[c]          (QKV scatter)
// mode 1: out[r*D + c]   = acc + bias[c] + resid  (O-proj + residual)
// =================================================================
__global__ void __launch_bounds__(256) gemm128(
    const float* __restrict__ A, const float* __restrict__ W,
    const float* __restrict__ bias, const float* __restrict__ resid,
    float* __restrict__ out, int mode)
{
    __shared__ float As[8][128];   // As[k][row]
    __shared__ float Bs[8][128];   // Bs[k][col]

    const int tid  = threadIdx.x;
    const int row0 = blockIdx.y * 128;
    const int col0 = blockIdx.x * 128;
    const int ty = tid >> 4;       // 0..15 -> rows 8*ty
    const int tx = tid & 15;       // 0..15 -> cols 8*tx

    float acc[8][8];
#pragma unroll
    for (int i = 0; i < 8; i++)
#pragma unroll
        for (int j = 0; j < 8; j++) acc[i][j] = 0.f;

    const int ar = tid >> 1;          // 0..127
    const int ak = (tid & 1) * 4;     // 0 or 4
    const int bk = tid >> 5;          // 0..7
    const int bc = (tid & 31) * 4;    // 0..124

    for (int k0 = 0; k0 < DD; k0 += 8) {
        float4 av = *(const float4*)(A + (size_t)(row0 + ar) * DD + k0 + ak);
        As[ak + 0][ar] = av.x;
        As[ak + 1][ar] = av.y;
        As[ak + 2][ar] = av.z;
        As[ak + 3][ar] = av.w;
        float4 bv = *(const float4*)(W + (size_t)(k0 + bk) * DD + col0 + bc);
        *(float4*)(&Bs[bk][bc]) = bv;
        __syncthreads();

#pragma unroll
        for (int k = 0; k < 8; k++) {
            float4 a0 = *(const float4*)(&As[k][ty * 8]);
            float4 a1 = *(const float4*)(&As[k][ty * 8 + 4]);
            float4 b0 = *(const float4*)(&Bs[k][tx * 8]);
            float4 b1 = *(const float4*)(&Bs[k][tx * 8 + 4]);
            float a[8] = {a0.x, a0.y, a0.z, a0.w, a1.x, a1.y, a1.z, a1.w};
            float b[8] = {b0.x, b0.y, b0.z, b0.w, b1.x, b1.y, b1.z, b1.w};
#pragma unroll
            for (int i = 0; i < 8; i++)
#pragma unroll
                for (int j = 0; j < 8; j++)
                    acc[i][j] += a[i] * b[j];
        }
        __syncthreads();
    }

#pragma unroll
    for (int i = 0; i < 8; i++) {
        const int r = row0 + ty * 8 + i;
#pragma unroll
        for (int j = 0; j < 8; j++) {
            const int c = col0 + tx * 8 + j;
            float v = acc[i][j] + bias[c];
            if (mode == 0) {
                const int b = r >> 11, s = r & 2047, h = c >> 6, d = c & 63;
                out[(((size_t)(b * HH + h)) * SS + s) * HDD + d] = v;
            } else {
                out[(size_t)r * DD + c] = v + resid[(size_t)r * DD + c];
            }
        }
    }
}

// =================================================================
// Flash attention, fp32. One block = 64 query rows of one (b,h).
// 256 threads: ty=tid/16 -> 4 q-rows (4*ty..+3), tx=tid%16 -> 4 cols.
// Online softmax over 64-key tiles. Writes ctx in [token, D] layout.
// =================================================================
#define PITCH 68          // pad to keep float4 alignment (68 % 4 == 0)
#define FLASH_SMEM (4 * 64 * PITCH * 4)

__global__ void __launch_bounds__(256) flash_attn(const float* __restrict__ mask)
{
    extern __shared__ float sm[];
    float* Qt = sm;                    // Qt[d][r]   (transposed)
    float* Kt = Qt + 64 * PITCH;       // Kt[d][k]   (transposed)
    float* Vs = Kt + 64 * PITCH;       // Vs[k][d]
    float* Pt = Vs + 64 * PITCH;       // Pt[k][r]

    const int tid = threadIdx.x;
    const int bh  = blockIdx.y;
    const int b = bh >> 4, h = bh & 15;
    const int q0 = blockIdx.x * 64;
    const int ty = tid >> 4;           // 0..15
    const int tx = tid & 15;           // 0..15

    const float* Qg = g_q + (size_t)(b * HH + h) * SS * HDD;
    const float* Kg = g_k + (size_t)(b * HH + h) * SS * HDD;
    const float* Vg = g_v + (size_t)(b * HH + h) * SS * HDD;
    const float* mrow = mask + (size_t)b * SS;

    // ---- load Q tile transposed: Qt[d][r] ----
    {
        const int r  = tid >> 2;          // 0..63
        const int d0 = (tid & 3) * 16;
#pragma unroll
        for (int u = 0; u < 16; u += 4) {
            float4 v = *(const float4*)(Qg + (size_t)(q0 + r) * HDD + d0 + u);
            Qt[(d0 + u + 0) * PITCH + r] = v.x;
            Qt[(d0 + u + 1) * PITCH + r] = v.y;
            Qt[(d0 + u + 2) * PITCH + r] = v.z;
            Qt[(d0 + u + 3) * PITCH + r] = v.w;
        }
    }

    float m_i[4], l_i[4], o_acc[4][4];
#pragma unroll
    for (int i = 0; i < 4; i++) {
        m_i[i] = -1e30f;
        l_i[i] = 0.f;
#pragma unroll
        for (int j = 0; j < 4; j++) o_acc[i][j] = 0.f;
    }

    const float scale = 0.125f;   // 1/sqrt(64)

    for (int k0 = 0; k0 < SS; k0 += 64) {
        __syncthreads();   // previous PV done before overwriting Kt/Vs
        // ---- load K (transposed) and V (natural) tiles ----
        {
            const int r  = tid >> 2;
            const int d0 = (tid & 3) * 16;
#pragma unroll
            for (int u = 0; u < 16; u += 4) {
                float4 kv = *(const float4*)(Kg + (size_t)(k0 + r) * HDD + d0 + u);
                Kt[(d0 + u + 0) * PITCH + r] = kv.x;
                Kt[(d0 + u + 1) * PITCH + r] = kv.y;
                Kt[(d0 + u + 2) * PITCH + r] = kv.z;
                Kt[(d0 + u + 3) * PITCH + r] = kv.w;
                float4 vv = *(const float4*)(Vg + (size_t)(k0 + r) * HDD + d0 + u);
                *(float4*)(&Vs[r * PITCH + d0 + u]) = vv;
            }
        }
        __syncthreads();

        // ---- scores: S[r][k] = sum_d Q[r][d] * K[k][d] ----
        float s_v[4][4];
#pragma unroll
        for (int i = 0; i < 4; i++)
#pragma unroll
            for (int j = 0; j < 4; j++) s_v[i][j] = 0.f;

#pragma unroll 8
        for (int d = 0; d < 64; d++) {
            float4 a = *(const float4*)(&Qt[d * PITCH + ty * 4]);
            float4 bk4 = *(const float4*)(&Kt[d * PITCH + tx * 4]);
            float aa[4] = {a.x, a.y, a.z, a.w};
            float bb[4] = {bk4.x, bk4.y, bk4.z, bk4.w};
#pragma unroll
            for (int i = 0; i < 4; i++)
#pragma unroll
                for (int j = 0; j < 4; j++)
                    s_v[i][j] += aa[i] * bb[j];
        }

        // mask (per-key) + scale
        float4 mv4 = *(const float4*)(mrow + k0 + tx * 4);
        float mv[4] = {mv4.x, mv4.y, mv4.z, mv4.w};
#pragma unroll
        for (int i = 0; i < 4; i++)
#pragma unroll
            for (int j = 0; j < 4; j++)
                s_v[i][j] = s_v[i][j] * scale + mv[j];

        // ---- online softmax (rows owned by the 16 lanes with same ty) ----
#pragma unroll
        for (int i = 0; i < 4; i++) {
            float mx = s_v[i][0];
#pragma unroll
            for (int j = 1; j < 4; j++) mx = fmaxf(mx, s_v[i][j]);
#pragma unroll
            for (int o = 1; o < 16; o <<= 1)
                mx = fmaxf(mx, __shfl_xor_sync(0xffffffffu, mx, o));

            float mnew = fmaxf(m_i[i], mx);
            float f = __expf(m_i[i] - mnew);
            float rs = 0.f;
#pragma unroll
            for (int j = 0; j < 4; j++) {
                float p = __expf(s_v[i][j] - mnew);
                s_v[i][j] = p;
                rs += p;
            }
#pragma unroll
            for (int o = 1; o < 16; o <<= 1)
                rs += __shfl_xor_sync(0xffffffffu, rs, o);

            l_i[i] = l_i[i] * f + rs;
            m_i[i] = mnew;
#pragma unroll
            for (int j = 0; j < 4; j++) o_acc[i][j] *= f;
        }

        // write P transposed: Pt[k][r]
#pragma unroll
        for (int i = 0; i < 4; i++)
#pragma unroll
            for (int j = 0; j < 4; j++)
                Pt[(tx * 4 + j) * PITCH + (ty * 4 + i)] = s_v[i][j];
        __syncthreads();

        // ---- PV: O[r][d] += sum_k P[r][k] * V[k][d] ----
#pragma unroll 8
        for (int k = 0; k < 64; k++) {
            float4 a = *(const float4*)(&Pt[k * PITCH + ty * 4]);
            float4 bv4 = *(const float4*)(&Vs[k * PITCH + tx * 4]);
            float aa[4] = {a.x, a.y, a.z, a.w};
            float bb[4] = {bv4.x, bv4.y, bv4.z, bv4.w};
#pragma unroll
            for (int i = 0; i < 4; i++)
#pragma unroll
                for (int j = 0; j < 4; j++)
                    o_acc[i][j] += aa[i] * bb[j];
        }
    }

    // ---- normalize and write ctx in [token, D] layout ----
    float* Cg = g_ctx + (size_t)(b * SS + q0) * DD + h * HDD;
#pragma unroll
    for (int i = 0; i < 4; i++) {
        float inv = 1.f / l_i[i];
        float4 o;
        o.x = o_acc[i][0] * inv;
        o.y = o_acc[i][1] * inv;
        o.z = o_acc[i][2] * inv;
        o.w = o_acc[i][3] * inv;
        *(float4*)(Cg + (size_t)(ty * 4 + i) * DD + tx * 4) = o;
    }
}

// =================================================================
// LayerNorm: one block per token row (1024 elems, 256 thr x float4)
// =================================================================
__device__ __forceinline__ float blockSum(float v, float* red)
{
    const int lane = threadIdx.x & 31, wid = threadIdx.x >> 5;
#pragma unroll
    for (int o = 16; o > 0; o >>= 1) v += __shfl_xor_sync(0xffffffffu, v, o);
    if (lane == 0) red[wid] = v;
    __syncthreads();
    if (wid == 0) {
        float t = (lane < 8) ? red[lane] : 0.f;
#pragma unroll
        for (int o = 4; o > 0; o >>= 1) t += __shfl_xor_sync(0xffffffffu, t, o);
        if (lane == 0) red[0] = t;
    }
    __syncthreads();
    float r = red[0];
    __syncthreads();
    return r;
}

__global__ void __launch_bounds__(256) ln_kernel(
    const float* __restrict__ x, const float* __restrict__ gamma,
    const float* __restrict__ beta, float* __restrict__ out)
{
    __shared__ float red[8];
    const int row = blockIdx.x;
    const int t = threadIdx.x;

    float4 v = ((const float4*)(x + (size_t)row * DD))[t];
    float s = v.x + v.y + v.z + v.w;
    float mu = blockSum(s, red) * (1.0f / DD);

    float dx0 = v.x - mu, dx1 = v.y - mu, dx2 = v.z - mu, dx3 = v.w - mu;
    float sq = dx0 * dx0 + dx1 * dx1 + dx2 * dx2 + dx3 * dx3;
    float var = blockSum(sq, red) * (1.0f / DD);
    float inv = rsqrtf(var + 1e-12f);

    float4 g = ((const float4*)gamma)[t];
    float4 b = ((const float4*)beta)[t];
    float4 o;
    o.x = dx0 * inv * g.x + b.x;
    o.y = dx1 * inv * g.y + b.y;
    o.z = dx2 * inv * g.z + b.z;
    o.w = dx3 * inv * g.w + b.w;
    ((float4*)(out + (size_t)row * DD))[t] = o;
}

// =================================================================
extern "C" void kernel_launch(void* const* d_in, const int* in_sizes, int n_in,
                              void* d_out, int out_size)
{
    const float* hidden = (const float*)d_in[0];
    const float* mask   = (const float*)d_in[1];
    const float* Wq     = (const float*)d_in[2];
    const float* bq     = (const float*)d_in[3];
    const float* Wk     = (const float*)d_in[4];
    const float* bk     = (const float*)d_in[5];
    const float* Wv     = (const float*)d_in[6];
    const float* bv     = (const float*)d_in[7];
    const float* Wo     = (const float*)d_in[8];
    const float* bo     = (const float*)d_in[9];
    const float* gamma  = (const float*)d_in[10];
    const float* beta   = (const float*)d_in[11];
    float* out = (float*)d_out;

    float *q, *k, *v, *ctx, *x;
    cudaGetSymbolAddress((void**)&q,   g_q);
    cudaGetSymbolAddress((void**)&k,   g_k);
    cudaGetSymbolAddress((void**)&v,   g_v);
    cudaGetSymbolAddress((void**)&ctx, g_ctx);
    cudaGetSymbolAddress((void**)&x,   g_x);

    cudaFuncSetAttribute(flash_attn,
                         cudaFuncAttributeMaxDynamicSharedMemorySize, FLASH_SMEM);

    dim3 gg(DD / 128, NT / 128);   // (8, 32)
    gemm128<<<gg, 256>>>(hidden, Wq, bq, nullptr, q, 0);
    gemm128<<<gg, 256>>>(hidden, Wk, bk, nullptr, k, 0);
    gemm128<<<gg, 256>>>(hidden, Wv, bv, nullptr, v, 0);

    flash_attn<<<dim3(SS / 64, BB * HH), 256, FLASH_SMEM>>>(mask);

    gemm128<<<gg, 256>>>(ctx, Wo, bo, hidden, x, 1);

    ln_kernel<<<NT, 256>>>(x, gamma, beta, out);
}

// round 3
// speedup vs baseline: 3.2745x; 3.2745x over previous
#include <cuda_runtime.h>
#include <cstdint>

#define BB  2
#define SS  2048
#define DD  1024
#define HH  16
#define HDD 64
#define NT  (BB * SS)   // 4096 tokens

// ---------------- scratch (no allocation allowed) ----------------
__device__ float g_q[NT * DD];    // [B,H,S,HD]
__device__ float g_k[NT * DD];    // [B,H,S,HD]
__device__ float g_v[NT * DD];    // [B,H,S,HD]
__device__ float g_ctx[NT * DD];  // [token, D]
__device__ float g_x[NT * DD];    // proj + residual, pre-LN

// ---------------- PTX helpers ----------------
__device__ __forceinline__ uint32_t f2tf(float f) {
    uint32_t r;
    asm("cvt.rna.tf32.f32 %0, %1;" : "=r"(r) : "f"(f));
    return r;
}
__device__ __forceinline__ void mma_tf32(float* c, const uint32_t* a, const uint32_t* b) {
    asm volatile(
        "mma.sync.aligned.m16n8k8.row.col.f32.tf32.tf32.f32 "
        "{%0,%1,%2,%3},{%4,%5,%6,%7},{%8,%9},{%0,%1,%2,%3};\n"
        : "+f"(c[0]), "+f"(c[1]), "+f"(c[2]), "+f"(c[3])
        : "r"(a[0]), "r"(a[1]), "r"(a[2]), "r"(a[3]), "r"(b[0]), "r"(b[1]));
}
__device__ __forceinline__ uint32_t smem_u32(const void* p) {
    return (uint32_t)__cvta_generic_to_shared(p);
}
__device__ __forceinline__ void cpa16(uint32_t s, const void* g) {
    asm volatile("cp.async.cg.shared.global [%0], [%1], 16;" :: "r"(s), "l"(g));
}
#define CP_COMMIT asm volatile("cp.async.commit_group;")
#define CP_WAIT1  asm volatile("cp.async.wait_group 1;")
#define CP_WAIT0  asm volatile("cp.async.wait_group 0;")

// =================================================================
// TF32 tensor-core GEMM. 128x128x32 tiles, 256 thr (8 warps, 2x4),
// warp tile 64x32, mma.m16n8k8. cp.async double buffered.
// A:[4096,1024] rm, W:[1024,1024] rm.
// mode 0: scatter out[(b,h,s,d)] = acc + bias[c]
// mode 1: out[r*D+c] = acc + bias[c] + resid[r*D+c]
// =================================================================
#define AP_G 36    // As pitch (floats): banks (g*4+c) unique
#define BP_G 136   // Bs pitch: banks (c*8+g) unique
#define GEMM_SMEM ((2*128*AP_G + 2*32*BP_G) * 4)

__global__ void __launch_bounds__(256) gemm_tf32(
    const float* __restrict__ A, const float* __restrict__ W,
    const float* __restrict__ bias, const float* __restrict__ resid,
    float* __restrict__ out, int mode)
{
    extern __shared__ float sm[];
    float* As = sm;                 // [2][128][AP_G]
    float* Bs = sm + 2 * 128 * AP_G; // [2][32][BP_G]

    const int tid  = threadIdx.x;
    const int warp = tid >> 5, lane = tid & 31;
    const int g = lane >> 2, c = lane & 3;
    const int wm = (warp >> 2) * 64, wn = (warp & 3) * 32;
    const int row0 = blockIdx.y * 128, col0 = blockIdx.x * 128;

    float acc[4][4][4];
#pragma unroll
    for (int mi = 0; mi < 4; mi++)
#pragma unroll
        for (int ni = 0; ni < 4; ni++)
#pragma unroll
            for (int r = 0; r < 4; r++) acc[mi][ni][r] = 0.f;

    // ---- tile loader (tile t -> buffer buf) ----
#define LOAD_TILE(t, buf)                                                      \
    {                                                                          \
        const int _t = (t), _b = (buf);                                        \
        _Pragma("unroll")                                                      \
        for (int i = 0; i < 4; i++) {                                          \
            int idx = tid + 256 * i;                                           \
            int r = idx >> 3, kc = (idx & 7) * 4;                              \
            cpa16(smem_u32(As + _b * 128 * AP_G + r * AP_G + kc),              \
                  A + (size_t)(row0 + r) * DD + _t * 32 + kc);                 \
        }                                                                      \
        _Pragma("unroll")                                                      \
        for (int i = 0; i < 4; i++) {                                          \
            int idx = tid + 256 * i;                                           \
            int r = idx >> 5, cc = (idx & 31) * 4;                             \
            cpa16(smem_u32(Bs + _b * 32 * BP_G + r * BP_G + cc),               \
                  W + (size_t)(_t * 32 + r) * DD + col0 + cc);                 \
        }                                                                      \
    }

    LOAD_TILE(0, 0); CP_COMMIT;
    LOAD_TILE(1, 1); CP_COMMIT;

    const int NTL = DD / 32;   // 32 k-tiles
    for (int t = 0; t < NTL; t++) {
        if (t == NTL - 1) { CP_WAIT0; } else { CP_WAIT1; }
        __syncthreads();

        const int buf = t & 1;
        const float* Ab = As + buf * 128 * AP_G;
        const float* Bb = Bs + buf * 32 * BP_G;
#pragma unroll
        for (int kk = 0; kk < 32; kk += 8) {
            uint32_t afr[4][4], bfr[4][2];
#pragma unroll
            for (int mi = 0; mi < 4; mi++) {
                const float* p = Ab + (wm + mi * 16) * AP_G + kk;
                afr[mi][0] = f2tf(p[g * AP_G + c]);
                afr[mi][1] = f2tf(p[(g + 8) * AP_G + c]);
                afr[mi][2] = f2tf(p[g * AP_G + c + 4]);
                afr[mi][3] = f2tf(p[(g + 8) * AP_G + c + 4]);
            }
#pragma unroll
            for (int ni = 0; ni < 4; ni++) {
                const float* p = Bb + kk * BP_G + wn + ni * 8 + g;
                bfr[ni][0] = f2tf(p[c * BP_G]);
                bfr[ni][1] = f2tf(p[(c + 4) * BP_G]);
            }
#pragma unroll
            for (int mi = 0; mi < 4; mi++)
#pragma unroll
                for (int ni = 0; ni < 4; ni++)
                    mma_tf32(acc[mi][ni], afr[mi], bfr[ni]);
        }
        __syncthreads();
        if (t + 2 < NTL) { LOAD_TILE(t + 2, buf); CP_COMMIT; }
    }

    // ---- epilogue ----
#pragma unroll
    for (int mi = 0; mi < 4; mi++) {
#pragma unroll
        for (int ni = 0; ni < 4; ni++) {
            const int col = col0 + wn + ni * 8 + 2 * c;
            const float b0 = bias[col], b1 = bias[col + 1];
            const int r1 = row0 + wm + mi * 16 + g;
            const int r2 = r1 + 8;
            if (mode == 0) {
                const int bb1 = r1 >> 11, s1 = r1 & 2047;
                const int bb2 = r2 >> 11, s2 = r2 & 2047;
                const int h = col >> 6, d = col & 63;
                float2 v1 = {acc[mi][ni][0] + b0, acc[mi][ni][1] + b1};
                float2 v2 = {acc[mi][ni][2] + b0, acc[mi][ni][3] + b1};
                *(float2*)(out + (((size_t)(bb1 * HH + h)) * SS + s1) * HDD + d) = v1;
                *(float2*)(out + (((size_t)(bb2 * HH + h)) * SS + s2) * HDD + d) = v2;
            } else {
                const float2 rr1 = *(const float2*)(resid + (size_t)r1 * DD + col);
                const float2 rr2 = *(const float2*)(resid + (size_t)r2 * DD + col);
                float2 v1 = {acc[mi][ni][0] + b0 + rr1.x, acc[mi][ni][1] + b1 + rr1.y};
                float2 v2 = {acc[mi][ni][2] + b0 + rr2.x, acc[mi][ni][3] + b1 + rr2.y};
                *(float2*)(out + (size_t)r1 * DD + col) = v1;
                *(float2*)(out + (size_t)r2 * DD + col) = v2;
            }
        }
    }
#undef LOAD_TILE
}

// =================================================================
// Flash attention, tf32 tensor cores. Block = 64 q-rows of one (b,h),
// 128 threads (4 warps, 16 rows each). Online softmax, 64-key tiles.
// =================================================================
#define AP 68
#define FLASH_SMEM ((4 * 64 * AP + 64) * 4)

__global__ void __launch_bounds__(128) flash_tf32(const float* __restrict__ mask)
{
    extern __shared__ float sm[];
    float* Qs = sm;                  // [64][AP]  (row, hd)
    float* Ks = Qs + 64 * AP;        // [64][AP]  (key, hd)
    float* Vt = Ks + 64 * AP;        // [64][AP]  (hd, key)  transposed
    float* Ps = Vt + 64 * AP;        // [64][AP]  (row, key)
    float* Ms = Ps + 64 * AP;        // [64] mask

    const int tid  = threadIdx.x;
    const int warp = tid >> 5, lane = tid & 31;
    const int g = lane >> 2, c = lane & 3;
    const int wr = warp * 16;        // warp's first q row (in tile)

    const int bh = blockIdx.y;
    const int b = bh >> 4, h = bh & 15;
    const int q0 = blockIdx.x * 64;

    const float* Qg = g_q + (size_t)(b * HH + h) * SS * HDD;
    const float* Kg = g_k + (size_t)(b * HH + h) * SS * HDD;
    const float* Vg = g_v + (size_t)(b * HH + h) * SS * HDD;
    const float* mrow = mask + (size_t)b * SS;

    // ---- load Q tile -> smem -> tf32 frags in regs ----
#pragma unroll
    for (int i = 0; i < 8; i++) {
        int idx = tid + 128 * i;
        int r = idx >> 4, cc = (idx & 15) * 4;
        cpa16(smem_u32(Qs + r * AP + cc), Qg + (size_t)(q0 + r) * HDD + cc);
    }
    CP_COMMIT; CP_WAIT0;
    __syncthreads();

    uint32_t qf[8][4];
#pragma unroll
    for (int ks = 0; ks < 8; ks++) {
        const int kk = ks * 8;
        qf[ks][0] = f2tf(Qs[(wr + g) * AP + kk + c]);
        qf[ks][1] = f2tf(Qs[(wr + g + 8) * AP + kk + c]);
        qf[ks][2] = f2tf(Qs[(wr + g) * AP + kk + c + 4]);
        qf[ks][3] = f2tf(Qs[(wr + g + 8) * AP + kk + c + 4]);
    }

    float m_i[2] = {-1e30f, -1e30f};
    float l_i[2] = {0.f, 0.f};
    float o[8][4];
#pragma unroll
    for (int ni = 0; ni < 8; ni++)
#pragma unroll
        for (int r = 0; r < 4; r++) o[ni][r] = 0.f;

    for (int kt = 0; kt < SS / 64; kt++) {
        const int k0 = kt * 64;
        __syncthreads();   // all warps done with previous Ks/Vt

        // K + mask via cp.async
#pragma unroll
        for (int i = 0; i < 8; i++) {
            int idx = tid + 128 * i;
            int r = idx >> 4, cc = (idx & 15) * 4;
            cpa16(smem_u32(Ks + r * AP + cc), Kg + (size_t)(k0 + r) * HDD + cc);
        }
        if (tid < 16) cpa16(smem_u32(Ms + tid * 4), mrow + k0 + tid * 4);
        CP_COMMIT;

        // V transposed (direct loads)
        {
            const int key = tid & 63, seg = (tid >> 6) * 32;
#pragma unroll
            for (int u = 0; u < 8; u++) {
                float4 v4 = *(const float4*)(Vg + (size_t)(k0 + key) * HDD + seg + u * 4);
                Vt[(seg + u * 4 + 0) * AP + key] = v4.x;
                Vt[(seg + u * 4 + 1) * AP + key] = v4.y;
                Vt[(seg + u * 4 + 2) * AP + key] = v4.z;
                Vt[(seg + u * 4 + 3) * AP + key] = v4.w;
            }
        }
        CP_WAIT0;
        __syncthreads();

        // ---- S = Q K^T ----
        float s[8][4];
#pragma unroll
        for (int ni = 0; ni < 8; ni++)
#pragma unroll
            for (int r = 0; r < 4; r++) s[ni][r] = 0.f;

#pragma unroll
        for (int ks = 0; ks < 8; ks++) {
            const int kk = ks * 8;
#pragma unroll
            for (int ni = 0; ni < 8; ni++) {
                uint32_t bfr[2];
                const float* p = Ks + (ni * 8 + g) * AP + kk;
                bfr[0] = f2tf(p[c]);
                bfr[1] = f2tf(p[c + 4]);
                mma_tf32(s[ni], qf[ks], bfr);
            }
        }

        // ---- scale + mask + online softmax ----
        float mx0 = -1e30f, mx1 = -1e30f;
#pragma unroll
        for (int ni = 0; ni < 8; ni++) {
            const int col = ni * 8 + 2 * c;
            const float mk0 = Ms[col], mk1 = Ms[col + 1];
            s[ni][0] = s[ni][0] * 0.125f + mk0;
            s[ni][1] = s[ni][1] * 0.125f + mk1;
            s[ni][2] = s[ni][2] * 0.125f + mk0;
            s[ni][3] = s[ni][3] * 0.125f + mk1;
            mx0 = fmaxf(mx0, fmaxf(s[ni][0], s[ni][1]));
            mx1 = fmaxf(mx1, fmaxf(s[ni][2], s[ni][3]));
        }
        mx0 = fmaxf(mx0, __shfl_xor_sync(0xffffffffu, mx0, 1));
        mx0 = fmaxf(mx0, __shfl_xor_sync(0xffffffffu, mx0, 2));
        mx1 = fmaxf(mx1, __shfl_xor_sync(0xffffffffu, mx1, 1));
        mx1 = fmaxf(mx1, __shfl_xor_sync(0xffffffffu, mx1, 2));

        const float mn0 = fmaxf(m_i[0], mx0);
        const float mn1 = fmaxf(m_i[1], mx1);
        const float f0 = __expf(m_i[0] - mn0);
        const float f1 = __expf(m_i[1] - mn1);

        float rs0 = 0.f, rs1 = 0.f;
#pragma unroll
        for (int ni = 0; ni < 8; ni++) {
            s[ni][0] = __expf(s[ni][0] - mn0);
            s[ni][1] = __expf(s[ni][1] - mn0);
            s[ni][2] = __expf(s[ni][2] - mn1);
            s[ni][3] = __expf(s[ni][3] - mn1);
            rs0 += s[ni][0] + s[ni][1];
            rs1 += s[ni][2] + s[ni][3];
        }
        rs0 += __shfl_xor_sync(0xffffffffu, rs0, 1);
        rs0 += __shfl_xor_sync(0xffffffffu, rs0, 2);
        rs1 += __shfl_xor_sync(0xffffffffu, rs1, 1);
        rs1 += __shfl_xor_sync(0xffffffffu, rs1, 2);

        l_i[0] = l_i[0] * f0 + rs0;
        l_i[1] = l_i[1] * f1 + rs1;
        m_i[0] = mn0; m_i[1] = mn1;

#pragma unroll
        for (int ni = 0; ni < 8; ni++) {
            o[ni][0] *= f0; o[ni][1] *= f0;
            o[ni][2] *= f1; o[ni][3] *= f1;
        }

        // ---- P -> smem (per-warp rows only) ----
#pragma unroll
        for (int ni = 0; ni < 8; ni++) {
            const int col = ni * 8 + 2 * c;
            Ps[(wr + g) * AP + col]     = s[ni][0];
            Ps[(wr + g) * AP + col + 1] = s[ni][1];
            Ps[(wr + g + 8) * AP + col]     = s[ni][2];
            Ps[(wr + g + 8) * AP + col + 1] = s[ni][3];
        }
        __syncwarp();

        // ---- O += P V ----
#pragma unroll
        for (int ks = 0; ks < 8; ks++) {
            const int kk = ks * 8;
            uint32_t pf[4];
            pf[0] = f2tf(Ps[(wr + g) * AP + kk + c]);
            pf[1] = f2tf(Ps[(wr + g + 8) * AP + kk + c]);
            pf[2] = f2tf(Ps[(wr + g) * AP + kk + c + 4]);
            pf[3] = f2tf(Ps[(wr + g + 8) * AP + kk + c + 4]);
#pragma unroll
            for (int ni = 0; ni < 8; ni++) {
                uint32_t bfr[2];
                const float* p = Vt + (ni * 8 + g) * AP + kk;
                bfr[0] = f2tf(p[c]);
                bfr[1] = f2tf(p[c + 4]);
                mma_tf32(o[ni], pf, bfr);
            }
        }
    }

    // ---- normalize, write ctx [token, D] ----
    const float inv0 = 1.f / l_i[0];
    const float inv1 = 1.f / l_i[1];
    float* Cg = g_ctx + (size_t)(b * SS + q0) * DD + h * HDD;
#pragma unroll
    for (int ni = 0; ni < 8; ni++) {
        const int col = ni * 8 + 2 * c;
        float2 v1 = {o[ni][0] * inv0, o[ni][1] * inv0};
        float2 v2 = {o[ni][2] * inv1, o[ni][3] * inv1};
        *(float2*)(Cg + (size_t)(wr + g) * DD + col) = v1;
        *(float2*)(Cg + (size_t)(wr + g + 8) * DD + col) = v2;
    }
}

// =================================================================
// LayerNorm: one block per token row (1024 elems, 256 thr x float4)
// =================================================================
__device__ __forceinline__ float blockSum(float v, float* red)
{
    const int lane = threadIdx.x & 31, wid = threadIdx.x >> 5;
#pragma unroll
    for (int o = 16; o > 0; o >>= 1) v += __shfl_xor_sync(0xffffffffu, v, o);
    if (lane == 0) red[wid] = v;
    __syncthreads();
    if (wid == 0) {
        float t = (lane < 8) ? red[lane] : 0.f;
#pragma unroll
        for (int o = 4; o > 0; o >>= 1) t += __shfl_xor_sync(0xffffffffu, t, o);
        if (lane == 0) red[0] = t;
    }
    __syncthreads();
    float r = red[0];
    __syncthreads();
    return r;
}

__global__ void __launch_bounds__(256) ln_kernel(
    const float* __restrict__ x, const float* __restrict__ gamma,
    const float* __restrict__ beta, float* __restrict__ out)
{
    __shared__ float red[8];
    const int row = blockIdx.x;
    const int t = threadIdx.x;

    float4 v = ((const float4*)(x + (size_t)row * DD))[t];
    float s = v.x + v.y + v.z + v.w;
    float mu = blockSum(s, red) * (1.0f / DD);

    float dx0 = v.x - mu, dx1 = v.y - mu, dx2 = v.z - mu, dx3 = v.w - mu;
    float sq = dx0 * dx0 + dx1 * dx1 + dx2 * dx2 + dx3 * dx3;
    float var = blockSum(sq, red) * (1.0f / DD);
    float inv = rsqrtf(var + 1e-12f);

    float4 g = ((const float4*)gamma)[t];
    float4 b = ((const float4*)beta)[t];
    float4 o;
    o.x = dx0 * inv * g.x + b.x;
    o.y = dx1 * inv * g.y + b.y;
    o.z = dx2 * inv * g.z + b.z;
    o.w = dx3 * inv * g.w + b.w;
    ((float4*)(out + (size_t)row * DD))[t] = o;
}

// =================================================================
extern "C" void kernel_launch(void* const* d_in, const int* in_sizes, int n_in,
                              void* d_out, int out_size)
{
    const float* hidden = (const float*)d_in[0];
    const float* mask   = (const float*)d_in[1];
    const float* Wq     = (const float*)d_in[2];
    const float* bq     = (const float*)d_in[3];
    const float* Wk     = (const float*)d_in[4];
    const float* bk     = (const float*)d_in[5];
    const float* Wv     = (const float*)d_in[6];
    const float* bv     = (const float*)d_in[7];
    const float* Wo     = (const float*)d_in[8];
    const float* bo     = (const float*)d_in[9];
    const float* gamma  = (const float*)d_in[10];
    const float* beta   = (const float*)d_in[11];
    float* out = (float*)d_out;

    float *q, *k, *v, *ctx, *x;
    cudaGetSymbolAddress((void**)&q,   g_q);
    cudaGetSymbolAddress((void**)&k,   g_k);
    cudaGetSymbolAddress((void**)&v,   g_v);
    cudaGetSymbolAddress((void**)&ctx, g_ctx);
    cudaGetSymbolAddress((void**)&x,   g_x);

    cudaFuncSetAttribute(gemm_tf32,
                         cudaFuncAttributeMaxDynamicSharedMemorySize, GEMM_SMEM);
    cudaFuncSetAttribute(flash_tf32,
                         cudaFuncAttributeMaxDynamicSharedMemorySize, FLASH_SMEM);

    dim3 gg(DD / 128, NT / 128);   // (8, 32)
    gemm_tf32<<<gg, 256, GEMM_SMEM>>>(hidden, Wq, bq, nullptr, q, 0);
    gemm_tf32<<<gg, 256, GEMM_SMEM>>>(hidden, Wk, bk, nullptr, k, 0);
    gemm_tf32<<<gg, 256, GEMM_SMEM>>>(hidden, Wv, bv, nullptr, v, 0);

    flash_tf32<<<dim3(SS / 64, BB * HH), 128, FLASH_SMEM>>>(mask);

    gemm_tf32<<<gg, 256, GEMM_SMEM>>>(ctx, Wo, bo, hidden, x, 1);

    ln_kernel<<<NT, 256>>>(x, gamma, beta, out);
}

// round 4
// speedup vs baseline: 4.0303x; 1.2308x over previous
#include <cuda_runtime.h>
#include <cstdint>

#define BB  2
#define SS  2048
#define DD  1024
#define HH  16
#define HDD 64
#define NT  (BB * SS)   // 4096 tokens

// ---------------- scratch (no allocation allowed) ----------------
__device__ float g_q[NT * DD];    // [B,H,S,HD]
__device__ float g_k[NT * DD];    // [B,H,S,HD]
__device__ float g_v[NT * DD];    // [B,H,S,HD]
__device__ float g_ctx[NT * DD];  // [token, D]
__device__ float g_x[NT * DD];    // proj + residual, pre-LN

// ---------------- PTX helpers ----------------
// tf32 mma reads only the top 19 bits of each 32-bit operand; we pass raw
// fp32 bits (truncation instead of cvt.rna) to eliminate ALU conversions.
__device__ __forceinline__ uint32_t fbits(float f) { return __float_as_uint(f); }

__device__ __forceinline__ void mma_tf32(float* c, const uint32_t* a, const uint32_t* b) {
    asm volatile(
        "mma.sync.aligned.m16n8k8.row.col.f32.tf32.tf32.f32 "
        "{%0,%1,%2,%3},{%4,%5,%6,%7},{%8,%9},{%0,%1,%2,%3};\n"
        : "+f"(c[0]), "+f"(c[1]), "+f"(c[2]), "+f"(c[3])
        : "r"(a[0]), "r"(a[1]), "r"(a[2]), "r"(a[3]), "r"(b[0]), "r"(b[1]));
}
__device__ __forceinline__ uint32_t smem_u32(const void* p) {
    return (uint32_t)__cvta_generic_to_shared(p);
}
__device__ __forceinline__ void cpa16(uint32_t s, const void* g) {
    asm volatile("cp.async.cg.shared.global [%0], [%1], 16;" :: "r"(s), "l"(g));
}
#define CP_COMMIT asm volatile("cp.async.commit_group;")
#define CP_WAIT1  asm volatile("cp.async.wait_group 1;")
#define CP_WAIT0  asm volatile("cp.async.wait_group 0;")

// =================================================================
// TF32 tensor-core GEMM. 128x128x32 tiles, 256 thr (8 warps, 2x4),
// warp tile 64x32, mma.m16n8k8. cp.async double buffered.
// A:[4096,1024] rm, W:[1024,1024] rm.
// mode 0: scatter out[(b,h,s,d)] = acc + bias[c]
// mode 1: out[r*D+c] = acc + bias[c] + resid[r*D+c]
// =================================================================
#define AP_G 36    // As pitch (floats): banks (g*4+c) unique
#define BP_G 136   // Bs pitch: banks (c*8+g) unique
#define GEMM_SMEM ((2*128*AP_G + 2*32*BP_G) * 4)

__global__ void __launch_bounds__(256) gemm_tf32(
    const float* __restrict__ A, const float* __restrict__ W,
    const float* __restrict__ bias, const float* __restrict__ resid,
    float* __restrict__ out, int mode)
{
    extern __shared__ float sm[];
    float* As = sm;                  // [2][128][AP_G]
    float* Bs = sm + 2 * 128 * AP_G; // [2][32][BP_G]

    const int tid  = threadIdx.x;
    const int warp = tid >> 5, lane = tid & 31;
    const int g = lane >> 2, c = lane & 3;
    const int wm = (warp >> 2) * 64, wn = (warp & 3) * 32;
    const int row0 = blockIdx.y * 128, col0 = blockIdx.x * 128;

    float acc[4][4][4];
#pragma unroll
    for (int mi = 0; mi < 4; mi++)
#pragma unroll
        for (int ni = 0; ni < 4; ni++)
#pragma unroll
            for (int r = 0; r < 4; r++) acc[mi][ni][r] = 0.f;

#define LOAD_TILE(t, buf)                                                      \
    {                                                                          \
        const int _t = (t), _b = (buf);                                        \
        _Pragma("unroll")                                                      \
        for (int i = 0; i < 4; i++) {                                          \
            int idx = tid + 256 * i;                                           \
            int r = idx >> 3, kc = (idx & 7) * 4;                              \
            cpa16(smem_u32(As + _b * 128 * AP_G + r * AP_G + kc),              \
                  A + (size_t)(row0 + r) * DD + _t * 32 + kc);                 \
        }                                                                      \
        _Pragma("unroll")                                                      \
        for (int i = 0; i < 4; i++) {                                          \
            int idx = tid + 256 * i;                                           \
            int r = idx >> 5, cc = (idx & 31) * 4;                             \
            cpa16(smem_u32(Bs + _b * 32 * BP_G + r * BP_G + cc),               \
                  W + (size_t)(_t * 32 + r) * DD + col0 + cc);                 \
        }                                                                      \
    }

    LOAD_TILE(0, 0); CP_COMMIT;
    LOAD_TILE(1, 1); CP_COMMIT;

    const int NTL = DD / 32;   // 32 k-tiles
    for (int t = 0; t < NTL; t++) {
        if (t == NTL - 1) { CP_WAIT0; } else { CP_WAIT1; }
        __syncthreads();

        const int buf = t & 1;
        const float* Ab = As + buf * 128 * AP_G;
        const float* Bb = Bs + buf * 32 * BP_G;
#pragma unroll
        for (int kk = 0; kk < 32; kk += 8) {
            uint32_t afr[4][4], bfr[4][2];
#pragma unroll
            for (int mi = 0; mi < 4; mi++) {
                const float* p = Ab + (wm + mi * 16) * AP_G + kk;
                afr[mi][0] = fbits(p[g * AP_G + c]);
                afr[mi][1] = fbits(p[(g + 8) * AP_G + c]);
                afr[mi][2] = fbits(p[g * AP_G + c + 4]);
                afr[mi][3] = fbits(p[(g + 8) * AP_G + c + 4]);
            }
#pragma unroll
            for (int ni = 0; ni < 4; ni++) {
                const float* p = Bb + kk * BP_G + wn + ni * 8 + g;
                bfr[ni][0] = fbits(p[c * BP_G]);
                bfr[ni][1] = fbits(p[(c + 4) * BP_G]);
            }
#pragma unroll
            for (int mi = 0; mi < 4; mi++)
#pragma unroll
                for (int ni = 0; ni < 4; ni++)
                    mma_tf32(acc[mi][ni], afr[mi], bfr[ni]);
        }
        __syncthreads();
        if (t + 2 < NTL) { LOAD_TILE(t + 2, buf); CP_COMMIT; }
    }

    // ---- epilogue ----
#pragma unroll
    for (int mi = 0; mi < 4; mi++) {
#pragma unroll
        for (int ni = 0; ni < 4; ni++) {
            const int col = col0 + wn + ni * 8 + 2 * c;
            const float b0 = bias[col], b1 = bias[col + 1];
            const int r1 = row0 + wm + mi * 16 + g;
            const int r2 = r1 + 8;
            if (mode == 0) {
                const int bb1 = r1 >> 11, s1 = r1 & 2047;
                const int bb2 = r2 >> 11, s2 = r2 & 2047;
                const int h = col >> 6, d = col & 63;
                float2 v1 = {acc[mi][ni][0] + b0, acc[mi][ni][1] + b1};
                float2 v2 = {acc[mi][ni][2] + b0, acc[mi][ni][3] + b1};
                *(float2*)(out + (((size_t)(bb1 * HH + h)) * SS + s1) * HDD + d) = v1;
                *(float2*)(out + (((size_t)(bb2 * HH + h)) * SS + s2) * HDD + d) = v2;
            } else {
                const float2 rr1 = *(const float2*)(resid + (size_t)r1 * DD + col);
                const float2 rr2 = *(const float2*)(resid + (size_t)r2 * DD + col);
                float2 v1 = {acc[mi][ni][0] + b0 + rr1.x, acc[mi][ni][1] + b1 + rr1.y};
                float2 v2 = {acc[mi][ni][2] + b0 + rr2.x, acc[mi][ni][3] + b1 + rr2.y};
                *(float2*)(out + (size_t)r1 * DD + col) = v1;
                *(float2*)(out + (size_t)r2 * DD + col) = v2;
            }
        }
    }
#undef LOAD_TILE
}

// =================================================================
// Flash attention, tf32. Block = 64 q-rows of one (b,h), 128 thr
// (4 warps x 16 rows). K/V/mask double-buffered via cp.async.
// V kept natural [key][hd] (pitch 72 -> conflict-free transposed
// fragment reads). Ps aliases Qs. No cvt anywhere (raw fp32 bits).
// =================================================================
#define QP 68   // Qs/Ps pitch: frag reads bank (4g+c) -> conflict-free
#define KP 68   // Ks pitch:    frag reads bank (4g+c) -> conflict-free
#define VP 72   // Vs pitch:    transposed reads bank (8c+g) -> conflict-free
#define FLASH_SMEM ((64*QP + 2*64*KP + 2*64*VP + 2*64) * 4)

__global__ void __launch_bounds__(128) flash_tf32(const float* __restrict__ mask)
{
    extern __shared__ float sm[];
    float* Qs = sm;                   // [64][QP], reused as Ps after prologue
    float* Ps = sm;
    float* Ks = sm + 64 * QP;         // [2][64][KP]
    float* Vs = Ks + 2 * 64 * KP;     // [2][64][VP]
    float* Ms = Vs + 2 * 64 * VP;     // [2][64]

    const int tid  = threadIdx.x;
    const int warp = tid >> 5, lane = tid & 31;
    const int g = lane >> 2, c = lane & 3;
    const int wr = warp * 16;         // warp's first q row (in tile)

    const int bh = blockIdx.y;
    const int b = bh >> 4, h = bh & 15;
    const int q0 = blockIdx.x * 64;

    const float* Qg = g_q + (size_t)(b * HH + h) * SS * HDD;
    const float* Kg = g_k + (size_t)(b * HH + h) * SS * HDD;
    const float* Vg = g_v + (size_t)(b * HH + h) * SS * HDD;
    const float* mrow = mask + (size_t)b * SS;

    // ---- prologue: Q tile -> smem -> register frags ----
#pragma unroll
    for (int i = 0; i < 8; i++) {
        int idx = tid + 128 * i;
        int r = idx >> 4, cc = (idx & 15) * 4;
        cpa16(smem_u32(Qs + r * QP + cc), Qg + (size_t)(q0 + r) * HDD + cc);
    }
    CP_COMMIT; CP_WAIT0;
    __syncthreads();

    uint32_t qf[8][4];
#pragma unroll
    for (int ks = 0; ks < 8; ks++) {
        const int kk = ks * 8;
        qf[ks][0] = fbits(Qs[(wr + g) * QP + kk + c]);
        qf[ks][1] = fbits(Qs[(wr + g + 8) * QP + kk + c]);
        qf[ks][2] = fbits(Qs[(wr + g) * QP + kk + c + 4]);
        qf[ks][3] = fbits(Qs[(wr + g + 8) * QP + kk + c + 4]);
    }
    __syncthreads();   // Q consumed; Qs may now be reused as Ps

    float m_i[2] = {-1e30f, -1e30f};
    float l_i[2] = {0.f, 0.f};
    float o[8][4];
#pragma unroll
    for (int ni = 0; ni < 8; ni++)
#pragma unroll
        for (int r = 0; r < 4; r++) o[ni][r] = 0.f;

    // K+V+mask tile loader
#define LOAD_KV(k0v, bufv)                                                     \
    {                                                                          \
        const int _k0 = (k0v), _b = (bufv);                                    \
        _Pragma("unroll")                                                      \
        for (int i = 0; i < 8; i++) {                                          \
            int idx = tid + 128 * i;                                           \
            int r = idx >> 4, cc = (idx & 15) * 4;                             \
            cpa16(smem_u32(Ks + _b * 64 * KP + r * KP + cc),                   \
                  Kg + (size_t)(_k0 + r) * HDD + cc);                          \
            cpa16(smem_u32(Vs + _b * 64 * VP + r * VP + cc),                   \
                  Vg + (size_t)(_k0 + r) * HDD + cc);                          \
        }                                                                      \
        if (tid < 16) cpa16(smem_u32(Ms + _b * 64 + tid * 4),                  \
                            mrow + _k0 + tid * 4);                             \
    }

    LOAD_KV(0, 0); CP_COMMIT;

    const int NKT = SS / 64;   // 32 key tiles
    for (int kt = 0; kt < NKT; kt++) {
        const int buf = kt & 1;
        if (kt + 1 < NKT) { LOAD_KV((kt + 1) * 64, 1 - buf); CP_COMMIT; CP_WAIT1; }
        else              { CP_WAIT0; }
        __syncthreads();

        const float* Kb = Ks + buf * 64 * KP;
        const float* Vb = Vs + buf * 64 * VP;
        const float* Mb = Ms + buf * 64;

        // ---- S = Q K^T ----
        float s[8][4];
#pragma unroll
        for (int ni = 0; ni < 8; ni++)
#pragma unroll
            for (int r = 0; r < 4; r++) s[ni][r] = 0.f;

#pragma unroll
        for (int ks = 0; ks < 8; ks++) {
            const int kk = ks * 8;
#pragma unroll
            for (int ni = 0; ni < 8; ni++) {
                uint32_t bfr[2];
                const float* p = Kb + (ni * 8 + g) * KP + kk;
                bfr[0] = fbits(p[c]);
                bfr[1] = fbits(p[c + 4]);
                mma_tf32(s[ni], qf[ks], bfr);
            }
        }

        // ---- scale + mask + online softmax ----
        float mx0 = -1e30f, mx1 = -1e30f;
#pragma unroll
        for (int ni = 0; ni < 8; ni++) {
            const int col = ni * 8 + 2 * c;
            const float mk0 = Mb[col], mk1 = Mb[col + 1];
            s[ni][0] = s[ni][0] * 0.125f + mk0;
            s[ni][1] = s[ni][1] * 0.125f + mk1;
            s[ni][2] = s[ni][2] * 0.125f + mk0;
            s[ni][3] = s[ni][3] * 0.125f + mk1;
            mx0 = fmaxf(mx0, fmaxf(s[ni][0], s[ni][1]));
            mx1 = fmaxf(mx1, fmaxf(s[ni][2], s[ni][3]));
        }
        mx0 = fmaxf(mx0, __shfl_xor_sync(0xffffffffu, mx0, 1));
        mx0 = fmaxf(mx0, __shfl_xor_sync(0xffffffffu, mx0, 2));
        mx1 = fmaxf(mx1, __shfl_xor_sync(0xffffffffu, mx1, 1));
        mx1 = fmaxf(mx1, __shfl_xor_sync(0xffffffffu, mx1, 2));

        const float mn0 = fmaxf(m_i[0], mx0);
        const float mn1 = fmaxf(m_i[1], mx1);
        const float f0 = __expf(m_i[0] - mn0);
        const float f1 = __expf(m_i[1] - mn1);

        float rs0 = 0.f, rs1 = 0.f;
#pragma unroll
        for (int ni = 0; ni < 8; ni++) {
            s[ni][0] = __expf(s[ni][0] - mn0);
            s[ni][1] = __expf(s[ni][1] - mn0);
            s[ni][2] = __expf(s[ni][2] - mn1);
            s[ni][3] = __expf(s[ni][3] - mn1);
            rs0 += s[ni][0] + s[ni][1];
            rs1 += s[ni][2] + s[ni][3];
        }
        rs0 += __shfl_xor_sync(0xffffffffu, rs0, 1);
        rs0 += __shfl_xor_sync(0xffffffffu, rs0, 2);
        rs1 += __shfl_xor_sync(0xffffffffu, rs1, 1);
        rs1 += __shfl_xor_sync(0xffffffffu, rs1, 2);

        l_i[0] = l_i[0] * f0 + rs0;
        l_i[1] = l_i[1] * f1 + rs1;
        m_i[0] = mn0; m_i[1] = mn1;

#pragma unroll
        for (int ni = 0; ni < 8; ni++) {
            o[ni][0] *= f0; o[ni][1] *= f0;
            o[ni][2] *= f1; o[ni][3] *= f1;
        }

        // ---- P -> smem (per-warp rows only, float2 stores) ----
#pragma unroll
        for (int ni = 0; ni < 8; ni++) {
            const int col = ni * 8 + 2 * c;
            *(float2*)(Ps + (wr + g) * QP + col)     = make_float2(s[ni][0], s[ni][1]);
            *(float2*)(Ps + (wr + g + 8) * QP + col) = make_float2(s[ni][2], s[ni][3]);
        }
        __syncwarp();

        // ---- O += P V  (V read transposed from natural layout) ----
#pragma unroll
        for (int ks = 0; ks < 8; ks++) {
            const int kk = ks * 8;
            uint32_t pf[4];
            pf[0] = fbits(Ps[(wr + g) * QP + kk + c]);
            pf[1] = fbits(Ps[(wr + g + 8) * QP + kk + c]);
            pf[2] = fbits(Ps[(wr + g) * QP + kk + c + 4]);
            pf[3] = fbits(Ps[(wr + g + 8) * QP + kk + c + 4]);
#pragma unroll
            for (int ni = 0; ni < 8; ni++) {
                uint32_t bfr[2];
                bfr[0] = fbits(Vb[(kk + c) * VP + ni * 8 + g]);
                bfr[1] = fbits(Vb[(kk + c + 4) * VP + ni * 8 + g]);
                mma_tf32(o[ni], pf, bfr);
            }
        }
        __syncthreads();   // all warps done with buf before next prefetch overwrites it
    }
#undef LOAD_KV

    // ---- normalize, write ctx [token, D] ----
    const float inv0 = 1.f / l_i[0];
    const float inv1 = 1.f / l_i[1];
    float* Cg = g_ctx + (size_t)(b * SS + q0) * DD + h * HDD;
#pragma unroll
    for (int ni = 0; ni < 8; ni++) {
        const int col = ni * 8 + 2 * c;
        float2 v1 = {o[ni][0] * inv0, o[ni][1] * inv0};
        float2 v2 = {o[ni][2] * inv1, o[ni][3] * inv1};
        *(float2*)(Cg + (size_t)(wr + g) * DD + col) = v1;
        *(float2*)(Cg + (size_t)(wr + g + 8) * DD + col) = v2;
    }
}

// =================================================================
// LayerNorm: one block per token row (1024 elems, 256 thr x float4)
// =================================================================
__device__ __forceinline__ float blockSum(float v, float* red)
{
    const int lane = threadIdx.x & 31, wid = threadIdx.x >> 5;
#pragma unroll
    for (int o = 16; o > 0; o >>= 1) v += __shfl_xor_sync(0xffffffffu, v, o);
    if (lane == 0) red[wid] = v;
    __syncthreads();
    if (wid == 0) {
        float t = (lane < 8) ? red[lane] : 0.f;
#pragma unroll
        for (int o = 4; o > 0; o >>= 1) t += __shfl_xor_sync(0xffffffffu, t, o);
        if (lane == 0) red[0] = t;
    }
    __syncthreads();
    float r = red[0];
    __syncthreads();
    return r;
}

__global__ void __launch_bounds__(256) ln_kernel(
    const float* __restrict__ x, const float* __restrict__ gamma,
    const float* __restrict__ beta, float* __restrict__ out)
{
    __shared__ float red[8];
    const int row = blockIdx.x;
    const int t = threadIdx.x;

    float4 v = ((const float4*)(x + (size_t)row * DD))[t];
    float s = v.x + v.y + v.z + v.w;
    float mu = blockSum(s, red) * (1.0f / DD);

    float dx0 = v.x - mu, dx1 = v.y - mu, dx2 = v.z - mu, dx3 = v.w - mu;
    float sq = dx0 * dx0 + dx1 * dx1 + dx2 * dx2 + dx3 * dx3;
    float var = blockSum(sq, red) * (1.0f / DD);
    float inv = rsqrtf(var + 1e-12f);

    float4 g = ((const float4*)gamma)[t];
    float4 b = ((const float4*)beta)[t];
    float4 o;
    o.x = dx0 * inv * g.x + b.x;
    o.y = dx1 * inv * g.y + b.y;
    o.z = dx2 * inv * g.z + b.z;
    o.w = dx3 * inv * g.w + b.w;
    ((float4*)(out + (size_t)row * DD))[t] = o;
}

// =================================================================
extern "C" void kernel_launch(void* const* d_in, const int* in_sizes, int n_in,
                              void* d_out, int out_size)
{
    const float* hidden = (const float*)d_in[0];
    const float* mask   = (const float*)d_in[1];
    const float* Wq     = (const float*)d_in[2];
    const float* bq     = (const float*)d_in[3];
    const float* Wk     = (const float*)d_in[4];
    const float* bk     = (const float*)d_in[5];
    const float* Wv     = (const float*)d_in[6];
    const float* bv     = (const float*)d_in[7];
    const float* Wo     = (const float*)d_in[8];
    const float* bo     = (const float*)d_in[9];
    const float* gamma  = (const float*)d_in[10];
    const float* beta   = (const float*)d_in[11];
    float* out = (float*)d_out;

    float *q, *k, *v, *ctx, *x;
    cudaGetSymbolAddress((void**)&q,   g_q);
    cudaGetSymbolAddress((void**)&k,   g_k);
    cudaGetSymbolAddress((void**)&v,   g_v);
    cudaGetSymbolAddress((void**)&ctx, g_ctx);
    cudaGetSymbolAddress((void**)&x,   g_x);

    cudaFuncSetAttribute(gemm_tf32,
                         cudaFuncAttributeMaxDynamicSharedMemorySize, GEMM_SMEM);
    cudaFuncSetAttribute(flash_tf32,
                         cudaFuncAttributeMaxDynamicSharedMemorySize, FLASH_SMEM);

    dim3 gg(DD / 128, NT / 128);   // (8, 32)
    gemm_tf32<<<gg, 256, GEMM_SMEM>>>(hidden, Wq, bq, nullptr, q, 0);
    gemm_tf32<<<gg, 256, GEMM_SMEM>>>(hidden, Wk, bk, nullptr, k, 0);
    gemm_tf32<<<gg, 256, GEMM_SMEM>>>(hidden, Wv, bv, nullptr, v, 0);

    flash_tf32<<<dim3(SS / 64, BB * HH), 128, FLASH_SMEM>>>(mask);

    gemm_tf32<<<gg, 256, GEMM_SMEM>>>(ctx, Wo, bo, hidden, x, 1);

    ln_kernel<<<NT, 256>>>(x, gamma, beta, out);
}

// round 6
// speedup vs baseline: 7.0882x; 1.7587x over previous
#include <cuda_runtime.h>
#include <cuda_bf16.h>
#include <cstdint>

#define BB  2
#define SS  2048
#define DD  1024
#define HH  16
#define HDD 64
#define NT  (BB * SS)   // 4096 tokens

// ---------------- scratch (no allocation allowed) ----------------
__device__ __nv_bfloat16 g_hb[NT * DD];      // hidden, bf16
__device__ __nv_bfloat16 g_q[NT * DD];       // [B,H,S,HD] bf16
__device__ __nv_bfloat16 g_k[NT * DD];       // [B,H,S,HD] bf16
__device__ uint32_t      g_v[NT * DD / 2];   // [B,H,S/2,HD] words: {V[2s'][d],V[2s'+1][d]}
__device__ __nv_bfloat16 g_ctx[NT * DD];     // [token, D] bf16
__device__ float         g_x[NT * DD];       // proj + residual, fp32
__device__ uint32_t      g_wq[DD * DD / 2];  // packed: Wp[k/2][n] = {W[k][n],W[k+1][n]}
__device__ uint32_t      g_wk[DD * DD / 2];
__device__ uint32_t      g_wv[DD * DD / 2];
__device__ uint32_t      g_wo[DD * DD / 2];

// ---------------- helpers ----------------
__device__ __forceinline__ uint32_t pack_bf16(float a, float b) {
    __nv_bfloat162 t = __floats2bfloat162_rn(a, b);
    return *reinterpret_cast<uint32_t*>(&t);
}
__device__ __forceinline__ void mma_bf16(float* c, const uint32_t* a, const uint32_t* b) {
    asm volatile(
        "mma.sync.aligned.m16n8k16.row.col.f32.bf16.bf16.f32 "
        "{%0,%1,%2,%3},{%4,%5,%6,%7},{%8,%9},{%0,%1,%2,%3};\n"
        : "+f"(c[0]), "+f"(c[1]), "+f"(c[2]), "+f"(c[3])
        : "r"(a[0]), "r"(a[1]), "r"(a[2]), "r"(a[3]), "r"(b[0]), "r"(b[1]));
}
__device__ __forceinline__ uint32_t smem_u32(const void* p) {
    return (uint32_t)__cvta_generic_to_shared(p);
}
__device__ __forceinline__ void cpa16(uint32_t s, const void* g) {
    asm volatile("cp.async.cg.shared.global [%0], [%1], 16;" :: "r"(s), "l"(g));
}
#define CP_COMMIT asm volatile("cp.async.commit_group;")
#define CP_WAIT1  asm volatile("cp.async.wait_group 1;")
#define CP_WAIT0  asm volatile("cp.async.wait_group 0;")

// ---------------- conversion kernels ----------------
__global__ void __launch_bounds__(256) conv_h(const float* __restrict__ in,
                                              __nv_bfloat16* __restrict__ out)
{
    int i = (blockIdx.x * 256 + threadIdx.x) * 4;
    float4 v = *(const float4*)(in + i);
    uint2 w;
    w.x = pack_bf16(v.x, v.y);
    w.y = pack_bf16(v.z, v.w);
    *(uint2*)(out + i) = w;
}

__global__ void __launch_bounds__(256) pack_w(const float* __restrict__ W,
                                              uint32_t* __restrict__ Wp)
{
    int idx = blockIdx.x * 256 + threadIdx.x;      // over 512*1024
    int k2 = idx >> 10, n = idx & 1023;
    Wp[idx] = pack_bf16(W[(size_t)(2 * k2) * DD + n], W[(size_t)(2 * k2 + 1) * DD + n]);
}

// =================================================================
// BF16 tensor-core GEMM. 128x128x32 tiles, 256 thr (8 warps 2x4),
// warp tile 64x32, mma.m16n8k16, cp.async double buffered.
// A: bf16 [M,1024] rm.  Wp: packed words [512][1024].
// mode 0: Q/K scatter bf16 [B,H,S,HD]
// mode 2: V scatter s-pair-packed words
// mode 1: fp32 out = acc + bias + resid
// =================================================================
#define AP16 72   // A smem pitch in bf16 (36 words): frag bank (4g+c)
#define BPW  136  // B smem pitch in words: frag bank (8c+8ni+g)
#define GEMM_SMEM (2*128*AP16*2 + 2*16*BPW*4)   // 36864 + 17408 = 54272 B

__global__ void __launch_bounds__(256) gemm_bf16(
    const __nv_bfloat16* __restrict__ A, const uint32_t* __restrict__ Wp,
    const float* __restrict__ bias, const float* __restrict__ resid,
    void* __restrict__ out, int mode)
{
    extern __shared__ char smraw[];
    __nv_bfloat16* As = (__nv_bfloat16*)smraw;            // [2][128][AP16]
    uint32_t* Bs = (uint32_t*)(smraw + 2 * 128 * AP16 * 2); // [2][16][BPW]

    const int tid  = threadIdx.x;
    const int warp = tid >> 5, lane = tid & 31;
    const int g = lane >> 2, c = lane & 3;
    const int wm = (warp >> 2) * 64, wn = (warp & 3) * 32;
    const int row0 = blockIdx.y * 128, col0 = blockIdx.x * 128;

    float acc[4][4][4];
#pragma unroll
    for (int mi = 0; mi < 4; mi++)
#pragma unroll
        for (int ni = 0; ni < 4; ni++)
#pragma unroll
            for (int r = 0; r < 4; r++) acc[mi][ni][r] = 0.f;

#define LOAD_TILE(t, buf)                                                      \
    {                                                                          \
        const int _t = (t), _b = (buf);                                        \
        _Pragma("unroll")                                                      \
        for (int i = 0; i < 2; i++) {                                          \
            int idx = tid + 256 * i;                                           \
            int r = idx >> 2, kc = (idx & 3) * 8;                              \
            cpa16(smem_u32(As + _b * 128 * AP16 + r * AP16 + kc),              \
                  A + (size_t)(row0 + r) * DD + _t * 32 + kc);                 \
        }                                                                      \
        _Pragma("unroll")                                                      \
        for (int i = 0; i < 2; i++) {                                          \
            int idx = tid + 256 * i;                                           \
            int r = idx >> 5, cc = (idx & 31) * 4;                             \
            cpa16(smem_u32(Bs + _b * 16 * BPW + r * BPW + cc),                 \
                  Wp + (size_t)(_t * 16 + r) * DD + col0 + cc);                \
        }                                                                      \
    }

    LOAD_TILE(0, 0); CP_COMMIT;
    LOAD_TILE(1, 1); CP_COMMIT;

    const int NTL = DD / 32;
    for (int t = 0; t < NTL; t++) {
        if (t == NTL - 1) { CP_WAIT0; } else { CP_WAIT1; }
        __syncthreads();

        const int buf = t & 1;
        const uint32_t* A32 = (const uint32_t*)(As + buf * 128 * AP16);
        const uint32_t* B32 = Bs + buf * 16 * BPW;
#pragma unroll
        for (int s = 0; s < 2; s++) {
            uint32_t afr[4][4], bfr[4][2];
#pragma unroll
            for (int mi = 0; mi < 4; mi++) {
                const int base = (wm + mi * 16 + g) * 36 + s * 8 + c;
                afr[mi][0] = A32[base];
                afr[mi][1] = A32[base + 8 * 36];
                afr[mi][2] = A32[base + 4];
                afr[mi][3] = A32[base + 8 * 36 + 4];
            }
#pragma unroll
            for (int ni = 0; ni < 4; ni++) {
                const int bw = (s * 8 + c) * BPW + wn + ni * 8 + g;
                bfr[ni][0] = B32[bw];
                bfr[ni][1] = B32[bw + 4 * BPW];
            }
#pragma unroll
            for (int mi = 0; mi < 4; mi++)
#pragma unroll
                for (int ni = 0; ni < 4; ni++)
                    mma_bf16(acc[mi][ni], afr[mi], bfr[ni]);
        }
        __syncthreads();
        if (t + 2 < NTL) { LOAD_TILE(t + 2, buf); CP_COMMIT; }
    }

    // ---- epilogue ----
#pragma unroll
    for (int mi = 0; mi < 4; mi++) {
#pragma unroll
        for (int ni = 0; ni < 4; ni++) {
            const int col = col0 + wn + ni * 8 + 2 * c;
            const float b0 = bias[col], b1 = bias[col + 1];
            const int r1 = row0 + wm + mi * 16 + g;
            const int r2 = r1 + 8;
            const float v0 = acc[mi][ni][0] + b0, v1 = acc[mi][ni][1] + b1;
            const float v2 = acc[mi][ni][2] + b0, v3 = acc[mi][ni][3] + b1;
            if (mode == 0) {
                __nv_bfloat16* ob = (__nv_bfloat16*)out;
                const int bb1 = r1 >> 11, s1 = r1 & 2047;
                const int bb2 = r2 >> 11, s2 = r2 & 2047;
                const int h = col >> 6, d = col & 63;
                *(uint32_t*)(ob + (((size_t)(bb1 * HH + h)) * SS + s1) * HDD + d) = pack_bf16(v0, v1);
                *(uint32_t*)(ob + (((size_t)(bb2 * HH + h)) * SS + s2) * HDD + d) = pack_bf16(v2, v3);
            } else if (mode == 2) {
                __nv_bfloat16* ov = (__nv_bfloat16*)out;
                const int bb1 = r1 >> 11, s1 = r1 & 2047;
                const int bb2 = r2 >> 11, s2 = r2 & 2047;
                const int h = col >> 6, d = col & 63;
                ov[(((size_t)(bb1 * HH + h) * (SS / 2) + (s1 >> 1)) * HDD + d)     * 2 + (s1 & 1)] = __float2bfloat16(v0);
                ov[(((size_t)(bb1 * HH + h) * (SS / 2) + (s1 >> 1)) * HDD + d + 1) * 2 + (s1 & 1)] = __float2bfloat16(v1);
                ov[(((size_t)(bb2 * HH + h) * (SS / 2) + (s2 >> 1)) * HDD + d)     * 2 + (s2 & 1)] = __float2bfloat16(v2);
                ov[(((size_t)(bb2 * HH + h) * (SS / 2) + (s2 >> 1)) * HDD + d + 1) * 2 + (s2 & 1)] = __float2bfloat16(v3);
            } else {
                float* of = (float*)out;
                const float2 rr1 = *(const float2*)(resid + (size_t)r1 * DD + col);
                const float2 rr2 = *(const float2*)(resid + (size_t)r2 * DD + col);
                *(float2*)(of + (size_t)r1 * DD + col) = make_float2(v0 + rr1.x, v1 + rr1.y);
                *(float2*)(of + (size_t)r2 * DD + col) = make_float2(v2 + rr2.x, v3 + rr2.y);
            }
        }
    }
#undef LOAD_TILE
}

// =================================================================
// Flash attention, bf16 m16n8k16. Block = 64 q-rows of one (b,h),
// 128 thr (4 warps x 16 rows). K/V/mask double-buffered cp.async.
// Q/K smem bf16 pitch 72 (bank 4g+c). V s-pair-packed words pitch 72
// (bank 8c+8ni+g). P packed bf16x2 in Qs region (reused).
// =================================================================
#define QPW 36   // Q/K/P word pitch (72 bf16)
#define VPW 72   // V word pitch
#define FLASH_SMEM (64*QPW*4 + 2*64*QPW*4 + 2*32*VPW*4 + 2*64*4)  // 46592 B

__global__ void __launch_bounds__(128) flash_bf16(const float* __restrict__ mask)
{
    extern __shared__ char smraw[];
    uint32_t* Qs = (uint32_t*)smraw;            // [64][QPW], reused as Ps
    uint32_t* Ps = Qs;
    uint32_t* Ks = Qs + 64 * QPW;               // [2][64][QPW]
    uint32_t* Vs = Ks + 2 * 64 * QPW;           // [2][32][VPW]
    float*    Ms = (float*)(Vs + 2 * 32 * VPW); // [2][64]

    const int tid  = threadIdx.x;
    const int warp = tid >> 5, lane = tid & 31;
    const int g = lane >> 2, c = lane & 3;
    const int wr = warp * 16;

    const int bh = blockIdx.y;
    const int b = bh >> 4;
    const int q0 = blockIdx.x * 64;

    const __nv_bfloat16* Qg = g_q + (size_t)bh * SS * HDD;
    const __nv_bfloat16* Kg = g_k + (size_t)bh * SS * HDD;
    const uint32_t*      Vg = g_v + (size_t)bh * (SS / 2) * HDD;
    const float* mrow = mask + (size_t)b * SS;

    // ---- prologue: Q tile -> smem -> frags ----
#pragma unroll
    for (int i = 0; i < 4; i++) {
        int idx = tid + 128 * i;
        int r = idx >> 3, kc = (idx & 7) * 8;
        cpa16(smem_u32((__nv_bfloat16*)Qs + r * 72 + kc),
              Qg + (size_t)(q0 + r) * HDD + kc);
    }
    CP_COMMIT; CP_WAIT0;
    __syncthreads();

    uint32_t qf[4][4];
#pragma unroll
    for (int ks = 0; ks < 4; ks++) {
        const int base = (wr + g) * QPW + ks * 8 + c;
        qf[ks][0] = Qs[base];
        qf[ks][1] = Qs[base + 8 * QPW];
        qf[ks][2] = Qs[base + 4];
        qf[ks][3] = Qs[base + 8 * QPW + 4];
    }
    __syncthreads();   // Qs free -> Ps

    float m_i[2] = {-1e30f, -1e30f};
    float l_i[2] = {0.f, 0.f};
    float o[8][4];
#pragma unroll
    for (int ni = 0; ni < 8; ni++)
#pragma unroll
        for (int r = 0; r < 4; r++) o[ni][r] = 0.f;

#define LOAD_KV(k0v, bufv)                                                     \
    {                                                                          \
        const int _k0 = (k0v), _b = (bufv);                                    \
        _Pragma("unroll")                                                      \
        for (int i = 0; i < 4; i++) {                                          \
            int idx = tid + 128 * i;                                           \
            int r = idx >> 3, kc = (idx & 7) * 8;                              \
            cpa16(smem_u32((__nv_bfloat16*)(Ks + _b * 64 * QPW) + r * 72 + kc),\
                  Kg + (size_t)(_k0 + r) * HDD + kc);                          \
        }                                                                      \
        _Pragma("unroll")                                                      \
        for (int i = 0; i < 4; i++) {                                          \
            int idx = tid + 128 * i;                                           \
            int r = idx >> 4, cc = (idx & 15) * 4;                             \
            cpa16(smem_u32(Vs + _b * 32 * VPW + r * VPW + cc),                 \
                  Vg + (size_t)(_k0 / 2 + r) * HDD + cc);                      \
        }                                                                      \
        if (tid < 16) cpa16(smem_u32(Ms + _b * 64 + tid * 4),                  \
                            mrow + _k0 + tid * 4);                             \
    }

    LOAD_KV(0, 0); CP_COMMIT;

    const int NKT = SS / 64;
    for (int kt = 0; kt < NKT; kt++) {
        const int buf = kt & 1;
        if (kt + 1 < NKT) { LOAD_KV((kt + 1) * 64, 1 - buf); CP_COMMIT; CP_WAIT1; }
        else              { CP_WAIT0; }
        __syncthreads();

        const uint32_t* Kb = Ks + buf * 64 * QPW;
        const uint32_t* Vb = Vs + buf * 32 * VPW;
        const float* Mb = Ms + buf * 64;

        // ---- S = Q K^T ----
        float s[8][4];
#pragma unroll
        for (int ni = 0; ni < 8; ni++)
#pragma unroll
            for (int r = 0; r < 4; r++) s[ni][r] = 0.f;

#pragma unroll
        for (int ks = 0; ks < 4; ks++) {
#pragma unroll
            for (int ni = 0; ni < 8; ni++) {
                uint32_t bfr[2];
                const int base = (ni * 8 + g) * QPW + ks * 8 + c;
                bfr[0] = Kb[base];
                bfr[1] = Kb[base + 4];
                mma_bf16(s[ni], qf[ks], bfr);
            }
        }

        // ---- scale + mask + online softmax ----
        float mx0 = -1e30f, mx1 = -1e30f;
#pragma unroll
        for (int ni = 0; ni < 8; ni++) {
            const int col = ni * 8 + 2 * c;
            const float mk0 = Mb[col], mk1 = Mb[col + 1];
            s[ni][0] = s[ni][0] * 0.125f + mk0;
            s[ni][1] = s[ni][1] * 0.125f + mk1;
            s[ni][2] = s[ni][2] * 0.125f + mk0;
            s[ni][3] = s[ni][3] * 0.125f + mk1;
            mx0 = fmaxf(mx0, fmaxf(s[ni][0], s[ni][1]));
            mx1 = fmaxf(mx1, fmaxf(s[ni][2], s[ni][3]));
        }
        mx0 = fmaxf(mx0, __shfl_xor_sync(0xffffffffu, mx0, 1));
        mx0 = fmaxf(mx0, __shfl_xor_sync(0xffffffffu, mx0, 2));
        mx1 = fmaxf(mx1, __shfl_xor_sync(0xffffffffu, mx1, 1));
        mx1 = fmaxf(mx1, __shfl_xor_sync(0xffffffffu, mx1, 2));

        const float mn0 = fmaxf(m_i[0], mx0);
        const float mn1 = fmaxf(m_i[1], mx1);
        const float f0 = __expf(m_i[0] - mn0);
        const float f1 = __expf(m_i[1] - mn1);

        float rs0 = 0.f, rs1 = 0.f;
#pragma unroll
        for (int ni = 0; ni < 8; ni++) {
            s[ni][0] = __expf(s[ni][0] - mn0);
            s[ni][1] = __expf(s[ni][1] - mn0);
            s[ni][2] = __expf(s[ni][2] - mn1);
            s[ni][3] = __expf(s[ni][3] - mn1);
            rs0 += s[ni][0] + s[ni][1];
            rs1 += s[ni][2] + s[ni][3];
        }
        rs0 += __shfl_xor_sync(0xffffffffu, rs0, 1);
        rs0 += __shfl_xor_sync(0xffffffffu, rs0, 2);
        rs1 += __shfl_xor_sync(0xffffffffu, rs1, 1);
        rs1 += __shfl_xor_sync(0xffffffffu, rs1, 2);

        l_i[0] = l_i[0] * f0 + rs0;
        l_i[1] = l_i[1] * f1 + rs1;
        m_i[0] = mn0; m_i[1] = mn1;

#pragma unroll
        for (int ni = 0; ni < 8; ni++) {
            o[ni][0] *= f0; o[ni][1] *= f0;
            o[ni][2] *= f1; o[ni][3] *= f1;
        }

        // ---- P -> smem as bf16x2 words (per-warp rows) ----
#pragma unroll
        for (int ni = 0; ni < 8; ni++) {
            Ps[(wr + g) * QPW + 4 * ni + c]     = pack_bf16(s[ni][0], s[ni][1]);
            Ps[(wr + g + 8) * QPW + 4 * ni + c] = pack_bf16(s[ni][2], s[ni][3]);
        }
        __syncwarp();

        // ---- O += P V ----
#pragma unroll
        for (int ks = 0; ks < 4; ks++) {
            uint32_t pf[4];
            const int pbase = (wr + g) * QPW + ks * 8 + c;
            pf[0] = Ps[pbase];
            pf[1] = Ps[pbase + 8 * QPW];
            pf[2] = Ps[pbase + 4];
            pf[3] = Ps[pbase + 8 * QPW + 4];
#pragma unroll
            for (int ni = 0; ni < 8; ni++) {
                uint32_t bfr[2];
                const int vb = (ks * 8 + c) * VPW + ni * 8 + g;
                bfr[0] = Vb[vb];
                bfr[1] = Vb[vb + 4 * VPW];
                mma_bf16(o[ni], pf, bfr);
            }
        }
        __syncthreads();
    }
#undef LOAD_KV

    // ---- normalize, write ctx bf16 [token, D] ----
    const float inv0 = 1.f / l_i[0];
    const float inv1 = 1.f / l_i[1];
    const int h = bh & 15;
    __nv_bfloat16* Cg = g_ctx + (size_t)(b * SS + q0) * DD + h * HDD;
#pragma unroll
    for (int ni = 0; ni < 8; ni++) {
        const int col = ni * 8 + 2 * c;
        *(uint32_t*)(Cg + (size_t)(wr + g) * DD + col)     = pack_bf16(o[ni][0] * inv0, o[ni][1] * inv0);
        *(uint32_t*)(Cg + (size_t)(wr + g + 8) * DD + col) = pack_bf16(o[ni][2] * inv1, o[ni][3] * inv1);
    }
}

// =================================================================
// LayerNorm
// =================================================================
__device__ __forceinline__ float blockSum(float v, float* red)
{
    const int lane = threadIdx.x & 31, wid = threadIdx.x >> 5;
#pragma unroll
    for (int o = 16; o > 0; o >>= 1) v += __shfl_xor_sync(0xffffffffu, v, o);
    if (lane == 0) red[wid] = v;
    __syncthreads();
    if (wid == 0) {
        float t = (lane < 8) ? red[lane] : 0.f;
#pragma unroll
        for (int o = 4; o > 0; o >>= 1) t += __shfl_xor_sync(0xffffffffu, t, o);
        if (lane == 0) red[0] = t;
    }
    __syncthreads();
    float r = red[0];
    __syncthreads();
    return r;
}

__global__ void __launch_bounds__(256) ln_kernel(
    const float* __restrict__ x, const float* __restrict__ gamma,
    const float* __restrict__ beta, float* __restrict__ out)
{
    __shared__ float red[8];
    const int row = blockIdx.x;
    const int t = threadIdx.x;

    float4 v = ((const float4*)(x + (size_t)row * DD))[t];
    float s = v.x + v.y + v.z + v.w;
    float mu = blockSum(s, red) * (1.0f / DD);

    float dx0 = v.x - mu, dx1 = v.y - mu, dx2 = v.z - mu, dx3 = v.w - mu;
    float sq = dx0 * dx0 + dx1 * dx1 + dx2 * dx2 + dx3 * dx3;
    float var = blockSum(sq, red) * (1.0f / DD);
    float inv = rsqrtf(var + 1e-12f);

    float4 g = ((const float4*)gamma)[t];
    float4 b = ((const float4*)beta)[t];
    float4 o;
    o.x = dx0 * inv * g.x + b.x;
    o.y = dx1 * inv * g.y + b.y;
    o.z = dx2 * inv * g.z + b.z;
    o.w = dx3 * inv * g.w + b.w;
    ((float4*)(out + (size_t)row * DD))[t] = o;
}

// =================================================================
extern "C" void kernel_launch(void* const* d_in, const int* in_sizes, int n_in,
                              void* d_out, int out_size)
{
    const float* hidden = (const float*)d_in[0];
    const float* mask   = (const float*)d_in[1];
    const float* Wq     = (const float*)d_in[2];
    const float* bq     = (const float*)d_in[3];
    const float* Wk     = (const float*)d_in[4];
    const float* bk     = (const float*)d_in[5];
    const float* Wv     = (const float*)d_in[6];
    const float* bv     = (const float*)d_in[7];
    const float* Wo     = (const float*)d_in[8];
    const float* bo     = (const float*)d_in[9];
    const float* gamma  = (const float*)d_in[10];
    const float* beta   = (const float*)d_in[11];
    float* out = (float*)d_out;

    __nv_bfloat16 *hb, *q, *k, *ctx;
    uint32_t *v, *wq, *wk, *wv, *wo;
    float *x;
    cudaGetSymbolAddress((void**)&hb,  g_hb);
    cudaGetSymbolAddress((void**)&q,   g_q);
    cudaGetSymbolAddress((void**)&k,   g_k);
    cudaGetSymbolAddress((void**)&v,   g_v);
    cudaGetSymbolAddress((void**)&ctx, g_ctx);
    cudaGetSymbolAddress((void**)&x,   g_x);
    cudaGetSymbolAddress((void**)&wq,  g_wq);
    cudaGetSymbolAddress((void**)&wk,  g_wk);
    cudaGetSymbolAddress((void**)&wv,  g_wv);
    cudaGetSymbolAddress((void**)&wo,  g_wo);

    cudaFuncSetAttribute(gemm_bf16,
                         cudaFuncAttributeMaxDynamicSharedMemorySize, GEMM_SMEM);
    cudaFuncSetAttribute(flash_bf16,
                         cudaFuncAttributeMaxDynamicSharedMemorySize, FLASH_SMEM);

    // conversions
    conv_h<<<NT * DD / 4 / 256, 256>>>(hidden, hb);
    pack_w<<<DD * DD / 2 / 256, 256>>>(Wq, wq);
    pack_w<<<DD * DD / 2 / 256, 256>>>(Wk, wk);
    pack_w<<<DD * DD / 2 / 256, 256>>>(Wv, wv);
    pack_w<<<DD * DD / 2 / 256, 256>>>(Wo, wo);

    dim3 gg(DD / 128, NT / 128);   // (8, 32)
    gemm_bf16<<<gg, 256, GEMM_SMEM>>>(hb, wq, bq, nullptr, q, 0);
    gemm_bf16<<<gg, 256, GEMM_SMEM>>>(hb, wk, bk, nullptr, k, 0);
    gemm_bf16<<<gg, 256, GEMM_SMEM>>>(hb, wv, bv, nullptr, v, 2);

    flash_bf16<<<dim3(SS / 64, BB * HH), 128, FLASH_SMEM>>>(mask);

    gemm_bf16<<<gg, 256, GEMM_SMEM>>>(ctx, wo, bo, hidden, x, 1);

    ln_kernel<<<NT, 256>>>(x, gamma, beta, out);
}